// round 9
// baseline (speedup 1.0000x reference)
#include <cuda_runtime.h>
#include <cstdint>

#define D_IN 256
#define D_OUT 128
#define SEGSZ 64
#define N_SEQ 2048

namespace {
constexpr int H_ST = D_OUT + 4;   // 132: conflict-free A-frag / ctx B-frag loads
constexpr int X_ST = 64 + 4;      // 68: 64-col k-chunks, 16B-aligned rows
constexpr int S_ST = 64 + 4;      // 68

constexpr int OFF_H = 0;                       // 64*132 = 8448 floats
constexpr int OFF_X = OFF_H + SEGSZ * H_ST;    // 8448
constexpr int XBUF  = SEGSZ * X_ST;            // 4352 floats per stage
constexpr int OFF_S = OFF_X;                   // Ss (64*68=4352) overlays X stage 0
constexpr int OFF_B = OFF_X + 2 * XBUF;        // 17152
constexpr int SMEM_FLOATS = OFF_B + D_OUT;     // 17280
constexpr int SMEM_BYTES  = SMEM_FLOATS * 4;   // 69120 B; x3 CTAs = 207360 <= 228KB/SM
} // namespace

// W in MMA B-fragment layout, tf32-rounded:
// g_wfrag[(k8*16 + ng)*32 + lane] = { W[k8*8 + (lane&3)][ng*8 + (lane>>2)],
//                                     W[k8*8 + (lane&3) + 4][ng*8 + (lane>>2)] }
__device__ float2 g_wfrag[32 * 16 * 32];

__device__ __forceinline__ float tf32r(float x) {
    uint32_t u = __float_as_uint(x);
    asm("cvt.rna.tf32.f32 %0, %1;" : "=r"(u) : "r"(u));
    return __uint_as_float(u);
}

__device__ __forceinline__ uint32_t tf32u(float x) {
    uint32_t u = __float_as_uint(x);
    asm("cvt.rna.tf32.f32 %0, %1;" : "=r"(u) : "r"(u));
    return u;
}

__device__ __forceinline__ void mma8(float* d, const uint32_t* a, const uint32_t* b) {
    asm volatile(
        "mma.sync.aligned.m16n8k8.row.col.f32.tf32.tf32.f32 "
        "{%0,%1,%2,%3}, {%4,%5,%6,%7}, {%8,%9}, {%0,%1,%2,%3};\n"
        : "+f"(d[0]), "+f"(d[1]), "+f"(d[2]), "+f"(d[3])
        : "r"(a[0]), "r"(a[1]), "r"(a[2]), "r"(a[3]), "r"(b[0]), "r"(b[1]));
}

__device__ __forceinline__ void cp_async16(uint32_t dst_smem, const void* src) {
    asm volatile("cp.async.cg.shared.global [%0], [%1], 16;\n"
                 :: "r"(dst_smem), "l"(src) : "memory");
}

__global__ __launch_bounds__(256)
void prep_w_kernel(const float* __restrict__ Wg) {
    int i = blockIdx.x * 256 + threadIdx.x;   // 0..16383
    int k8i = i >> 9;
    int ng  = (i >> 5) & 15;
    int ln  = i & 31;
    int row = k8i * 8 + (ln & 3);
    int col = ng * 8 + (ln >> 2);
    g_wfrag[i] = make_float2(tf32r(Wg[row * D_OUT + col]),
                             tf32r(Wg[(row + 4) * D_OUT + col]));
}

__global__ __launch_bounds__(256, 3)
void attn_hidden_kernel(const float* __restrict__ Xall,
                        const float* __restrict__ bg,
                        float* __restrict__ out)
{
    extern __shared__ float smem[];
    float* hs = smem + OFF_H;
    float* Ss = smem + OFF_S;    // overlays X stages (phase-disjoint)
    float* bs = smem + OFF_B;

    const int tid  = threadIdx.x;
    const int warp = tid >> 5;
    const int lane = tid & 31;
    const int lr   = lane >> 2;
    const int lc   = lane & 3;

    // 2x4 warp grid: GEMM/ctx warp tile = 32 rows x 32 cols
    const int m0  = (warp & 1) * 32;
    const int nq  = warp >> 1;       // 0..3
    const int n0  = nq * 32;
    const int n0s = nq * 16;         // S phase: 32 rows x 16 cols

    const int g = blockIdx.x;        // one CTA per segment
    const float* Xg = Xall + (size_t)g * SEGSZ * D_IN;

    if (tid < D_OUT) bs[tid] = bg[tid];

    const uint32_t xs_s0 = (uint32_t)__cvta_generic_to_shared(smem + OFF_X);

    // issue X chunk 0 (64 rows x 64 cols, 4x16B per thread)
    #pragma unroll
    for (int t = 0; t < 4; ++t) {
        int j = tid + t * 256;           // 0..1023 float4s
        int row = j >> 4, q = j & 15;
        cp_async16(xs_s0 + (row * X_ST + q * 4) * 4, Xg + row * D_IN + q * 4);
    }
    asm volatile("cp.async.commit_group;\n" ::: "memory");

    // ================= GEMM: h = X(64x256) @ W(256x128) =================
    float acc[2][4][4];
    #pragma unroll
    for (int mt = 0; mt < 2; ++mt)
        #pragma unroll
        for (int nt = 0; nt < 4; ++nt)
            #pragma unroll
            for (int i = 0; i < 4; ++i) acc[mt][nt][i] = 0.f;

    // register double-buffer of W B-fragments (W lives in L2)
    uint32_t bfr[2][4][2];
    #pragma unroll
    for (int nt = 0; nt < 4; ++nt) {
        float2 w2 = __ldg(&g_wfrag[(nq * 4 + nt) * 32 + lane]);   // k8g = 0
        bfr[0][nt][0] = __float_as_uint(w2.x);
        bfr[0][nt][1] = __float_as_uint(w2.y);
    }

    for (int kc = 0; kc < 4; ++kc) {
        __syncthreads();   // all warps done reading the stage about to be overwritten
        if (kc < 3) {
            const uint32_t dst = xs_s0 + ((kc + 1) & 1) * (XBUF * 4);
            #pragma unroll
            for (int t = 0; t < 4; ++t) {
                int j = tid + t * 256;
                int row = j >> 4, q = j & 15;
                cp_async16(dst + (row * X_ST + q * 4) * 4,
                           Xg + row * D_IN + (kc + 1) * 64 + q * 4);
            }
            asm volatile("cp.async.commit_group;\n" ::: "memory");
            asm volatile("cp.async.wait_group 1;\n" ::: "memory");
        } else {
            asm volatile("cp.async.wait_group 0;\n" ::: "memory");
        }
        __syncthreads();   // chunk kc visible to all warps

        const float* Xs = smem + OFF_X + (kc & 1) * XBUF;
        #pragma unroll
        for (int k8 = 0; k8 < 8; ++k8) {
            const int k8g = kc * 8 + k8;
            const int cur = k8g & 1;
            const int nk  = (k8g < 31) ? k8g + 1 : 31;   // prefetch next B frags
            #pragma unroll
            for (int nt = 0; nt < 4; ++nt) {
                float2 w2 = __ldg(&g_wfrag[(nk * 16 + nq * 4 + nt) * 32 + lane]);
                bfr[cur ^ 1][nt][0] = __float_as_uint(w2.x);
                bfr[cur ^ 1][nt][1] = __float_as_uint(w2.y);
            }
            const int kl = k8 * 8;
            uint32_t af[2][4];
            #pragma unroll
            for (int mt = 0; mt < 2; ++mt) {
                const float* p = Xs + (m0 + mt * 16 + lr) * X_ST + kl + lc;
                af[mt][0] = tf32u(p[0]);
                af[mt][1] = tf32u(p[8 * X_ST]);
                af[mt][2] = tf32u(p[4]);
                af[mt][3] = tf32u(p[8 * X_ST + 4]);
            }
            #pragma unroll
            for (int mt = 0; mt < 2; ++mt)
                #pragma unroll
                for (int nt = 0; nt < 4; ++nt)
                    mma8(acc[mt][nt], af[mt], bfr[cur][nt]);
        }
    }

    // epilogue: h (+bias), tf32-rounded -> smem
    #pragma unroll
    for (int mt = 0; mt < 2; ++mt) {
        #pragma unroll
        for (int nt = 0; nt < 4; ++nt) {
            int row = m0 + mt * 16 + lr;
            int col = n0 + nt * 8 + 2 * lc;
            hs[row * H_ST + col]           = tf32r(acc[mt][nt][0] + bs[col]);
            hs[row * H_ST + col + 1]       = tf32r(acc[mt][nt][1] + bs[col + 1]);
            hs[(row + 8) * H_ST + col]     = tf32r(acc[mt][nt][2] + bs[col]);
            hs[(row + 8) * H_ST + col + 1] = tf32r(acc[mt][nt][3] + bs[col + 1]);
        }
    }
    __syncthreads();

    // ================= S = h @ h^T  (64x64, K=128) =================
    float accS[2][2][4];
    #pragma unroll
    for (int mt = 0; mt < 2; ++mt)
        #pragma unroll
        for (int nt = 0; nt < 2; ++nt)
            #pragma unroll
            for (int i = 0; i < 4; ++i) accS[mt][nt][i] = 0.f;

    #pragma unroll
    for (int k8 = 0; k8 < 16; ++k8) {
        const int kl = k8 * 8;
        uint32_t af[2][4];
        #pragma unroll
        for (int mt = 0; mt < 2; ++mt) {
            const float* p = hs + (m0 + mt * 16 + lr) * H_ST + kl + lc;
            af[mt][0] = __float_as_uint(p[0]);
            af[mt][1] = __float_as_uint(p[8 * H_ST]);
            af[mt][2] = __float_as_uint(p[4]);
            af[mt][3] = __float_as_uint(p[8 * H_ST + 4]);
        }
        uint32_t bf[2][2];
        #pragma unroll
        for (int nt = 0; nt < 2; ++nt) {
            const float* p = hs + (n0s + nt * 8 + lr) * H_ST + kl + lc;
            bf[nt][0] = __float_as_uint(p[0]);
            bf[nt][1] = __float_as_uint(p[4]);
        }
        #pragma unroll
        for (int mt = 0; mt < 2; ++mt)
            #pragma unroll
            for (int nt = 0; nt < 2; ++nt)
                mma8(accS[mt][nt], af[mt], bf[nt]);
    }
    // store S raw fp32 (Ss overlays X; all warps past GEMM, sync'd at epilogue)
    #pragma unroll
    for (int mt = 0; mt < 2; ++mt) {
        #pragma unroll
        for (int nt = 0; nt < 2; ++nt) {
            int row = m0 + mt * 16 + lr;
            int col = n0s + nt * 8 + 2 * lc;
            Ss[row * S_ST + col]           = accS[mt][nt][0];
            Ss[row * S_ST + col + 1]       = accS[mt][nt][1];
            Ss[(row + 8) * S_ST + col]     = accS[mt][nt][2];
            Ss[(row + 8) * S_ST + col + 1] = accS[mt][nt][3];
        }
    }
    __syncthreads();

    // ================= softmax (row-wise), in place, P tf32 =================
    {
        const int srow = tid >> 2;      // 64 rows, 4 threads/row
        const int sq   = tid & 3;
        float4* rp = reinterpret_cast<float4*>(Ss + srow * S_ST + sq * 16);
        float v[16];
        #pragma unroll
        for (int j = 0; j < 4; ++j) {
            float4 t = rp[j];
            v[4*j] = t.x; v[4*j+1] = t.y; v[4*j+2] = t.z; v[4*j+3] = t.w;
        }
        float m = v[0];
        #pragma unroll
        for (int i = 1; i < 16; ++i) m = fmaxf(m, v[i]);
        m = fmaxf(m, __shfl_xor_sync(0xffffffffu, m, 1));
        m = fmaxf(m, __shfl_xor_sync(0xffffffffu, m, 2));
        float s = 0.f;
        #pragma unroll
        for (int i = 0; i < 16; ++i) { v[i] = __expf(v[i] - m); s += v[i]; }
        s += __shfl_xor_sync(0xffffffffu, s, 1);
        s += __shfl_xor_sync(0xffffffffu, s, 2);
        const float inv = 1.0f / s;
        #pragma unroll
        for (int j = 0; j < 4; ++j) {
            rp[j] = make_float4(tf32r(v[4*j] * inv),   tf32r(v[4*j+1] * inv),
                                tf32r(v[4*j+2] * inv), tf32r(v[4*j+3] * inv));
        }
    }
    __syncthreads();

    // ================= ctx = P(64x64) @ h(64x128) =================
    #pragma unroll
    for (int mt = 0; mt < 2; ++mt)
        #pragma unroll
        for (int nt = 0; nt < 4; ++nt)
            #pragma unroll
            for (int i = 0; i < 4; ++i) acc[mt][nt][i] = 0.f;

    #pragma unroll
    for (int k8 = 0; k8 < 8; ++k8) {
        const int kl = k8 * 8;
        uint32_t af[2][4];
        #pragma unroll
        for (int mt = 0; mt < 2; ++mt) {
            const float* p = Ss + (m0 + mt * 16 + lr) * S_ST + kl + lc;
            af[mt][0] = __float_as_uint(p[0]);
            af[mt][1] = __float_as_uint(p[8 * S_ST]);
            af[mt][2] = __float_as_uint(p[4]);
            af[mt][3] = __float_as_uint(p[8 * S_ST + 4]);
        }
        uint32_t bf[4][2];
        #pragma unroll
        for (int nt = 0; nt < 4; ++nt) {
            const float* p = hs + (kl + lc) * H_ST + n0 + nt * 8 + lr;
            bf[nt][0] = __float_as_uint(p[0]);
            bf[nt][1] = __float_as_uint(p[4 * H_ST]);
        }
        #pragma unroll
        for (int mt = 0; mt < 2; ++mt)
            #pragma unroll
            for (int nt = 0; nt < 4; ++nt)
                mma8(acc[mt][nt], af[mt], bf[nt]);
    }

    // store ctx to gmem
    #pragma unroll
    for (int mt = 0; mt < 2; ++mt) {
        #pragma unroll
        for (int nt = 0; nt < 4; ++nt) {
            size_t row = (size_t)g * SEGSZ + m0 + mt * 16 + lr;
            int col = n0 + nt * 8 + 2 * lc;
            *reinterpret_cast<float2*>(out + row * D_OUT + col) =
                make_float2(acc[mt][nt][0], acc[mt][nt][1]);
            *reinterpret_cast<float2*>(out + (row + 8) * D_OUT + col) =
                make_float2(acc[mt][nt][2], acc[mt][nt][3]);
        }
    }
}

extern "C" void kernel_launch(void* const* d_in, const int* in_sizes, int n_in,
                              void* d_out, int out_size) {
    (void)in_sizes; (void)n_in; (void)out_size;
    const float* X = (const float*)d_in[0];
    const float* W = (const float*)d_in[1];
    const float* b = (const float*)d_in[2];
    float* out = (float*)d_out;

    prep_w_kernel<<<64, 256>>>(W);   // 16384 fragment float2s

    cudaFuncSetAttribute(attn_hidden_kernel,
                         cudaFuncAttributeMaxDynamicSharedMemorySize, SMEM_BYTES);
    attn_hidden_kernel<<<N_SEQ, 256, SMEM_BYTES>>>(X, b, out);
}

// round 13
// speedup vs baseline: 1.4043x; 1.4043x over previous
#include <cuda_runtime.h>
#include <cstdint>

#define D_IN 256
#define D_OUT 128
#define SEGSZ 64
#define N_SEQ 2048

namespace {
constexpr int H_ST = D_OUT + 4;   // 132: conflict-free A-frag / ctx B-frag loads
constexpr int X_ST = 64 + 4;      // 68
constexpr int S_ST = 64 + 4;      // 68

constexpr int OFF_H = 0;                       // 64*132 = 8448 floats
constexpr int OFF_X = OFF_H + SEGSZ * H_ST;    // 8448 (4352 floats)
constexpr int OFF_S = OFF_X;                   // Ss (4352) overlays Xs (4352): phase-disjoint
constexpr int OFF_B = OFF_X + SEGSZ * X_ST;    // 12800
constexpr int SMEM_FLOATS = OFF_B + D_OUT;     // 12928
constexpr int SMEM_BYTES  = SMEM_FLOATS * 4;   // 51712 B; 2 CTAs -> ~124 KB L1D for W
} // namespace

// W in MMA B-fragment layout, tf32-rounded:
// g_wfrag[(k8*16 + ng)*32 + lane] = { W[k8*8 + (lane&3)][ng*8 + (lane>>2)],
//                                     W[k8*8 + (lane&3) + 4][ng*8 + (lane>>2)] }
__device__ float2 g_wfrag[32 * 16 * 32];

__device__ __forceinline__ float tf32r(float x) {
    uint32_t u = __float_as_uint(x);
    asm("cvt.rna.tf32.f32 %0, %1;" : "=r"(u) : "r"(u));
    return __uint_as_float(u);
}

__device__ __forceinline__ void mma8(float* d, const uint32_t* a, const uint32_t* b) {
    asm volatile(
        "mma.sync.aligned.m16n8k8.row.col.f32.tf32.tf32.f32 "
        "{%0,%1,%2,%3}, {%4,%5,%6,%7}, {%8,%9}, {%0,%1,%2,%3};\n"
        : "+f"(d[0]), "+f"(d[1]), "+f"(d[2]), "+f"(d[3])
        : "r"(a[0]), "r"(a[1]), "r"(a[2]), "r"(a[3]), "r"(b[0]), "r"(b[1]));
}

__global__ __launch_bounds__(256)
void prep_w_kernel(const float* __restrict__ Wg) {
    int i = blockIdx.x * 256 + threadIdx.x;   // 0..16383
    int k8i = i >> 9;
    int ng  = (i >> 5) & 15;
    int ln  = i & 31;
    int row = k8i * 8 + (ln & 3);
    int col = ng * 8 + (ln >> 2);
    g_wfrag[i] = make_float2(tf32r(Wg[row * D_OUT + col]),
                             tf32r(Wg[(row + 4) * D_OUT + col]));
}

__global__ __launch_bounds__(256, 2)
void attn_hidden_kernel(const float* __restrict__ Xall,
                        const float* __restrict__ bg,
                        float* __restrict__ out)
{
    extern __shared__ float smem[];
    float* hs = smem + OFF_H;
    float* Xs = smem + OFF_X;
    float* Ss = smem + OFF_S;    // alias of Xs (phase-disjoint)
    float* bs = smem + OFF_B;

    const int tid  = threadIdx.x;
    const int warp = tid >> 5;
    const int lane = tid & 31;
    const int lr   = lane >> 2;
    const int lc   = lane & 3;

    // 2x4 warp grid: GEMM/ctx warp tile = 32 rows x 32 cols
    const int m0  = (warp & 1) * 32;
    const int nq  = warp >> 1;       // 0..3
    const int n0  = nq * 32;
    const int n0s = nq * 16;         // S phase: 32 rows x 16 cols

    const int g = blockIdx.x;        // one CTA per segment
    const float* Xg = Xall + (size_t)g * SEGSZ * D_IN;

    if (tid < D_OUT) bs[tid] = bg[tid];

    // ================= GEMM: h = X(64x256) @ W(256x128) =================
    float acc[2][4][4];
    #pragma unroll
    for (int mt = 0; mt < 2; ++mt)
        #pragma unroll
        for (int nt = 0; nt < 4; ++nt)
            #pragma unroll
            for (int i = 0; i < 4; ++i) acc[mt][nt][i] = 0.f;

    // register double-buffer (prefetch distance 1) of W B-fragments (R6-proven)
    uint32_t bfr[2][4][2];
    #pragma unroll
    for (int nt = 0; nt < 4; ++nt) {
        float2 w2 = __ldg(&g_wfrag[(nq * 4 + nt) * 32 + lane]);   // k8g = 0
        bfr[0][nt][0] = __float_as_uint(w2.x);
        bfr[0][nt][1] = __float_as_uint(w2.y);
    }

    // prefetch X chunk 0 into regs (16 floats/thread)
    float4 pre[4];
    #pragma unroll
    for (int t = 0; t < 4; ++t) {
        int idx = tid + t * 256;
        int row = idx >> 4, q = idx & 15;
        pre[t] = *reinterpret_cast<const float4*>(Xg + row * D_IN + q * 4);
    }

    for (int kc = 0; kc < 4; ++kc) {
        if (kc > 0) __syncthreads();   // all warps done reading Xs (prev chunk)
        #pragma unroll
        for (int t = 0; t < 4; ++t) {
            int idx = tid + t * 256;
            int row = idx >> 4, q = idx & 15;
            float4 r4 = make_float4(tf32r(pre[t].x), tf32r(pre[t].y),
                                    tf32r(pre[t].z), tf32r(pre[t].w));
            *reinterpret_cast<float4*>(Xs + row * X_ST + q * 4) = r4;
        }
        __syncthreads();               // Xs ready (also covers bs on kc==0)
        if (kc < 3) {
            #pragma unroll
            for (int t = 0; t < 4; ++t) {
                int idx = tid + t * 256;
                int row = idx >> 4, q = idx & 15;
                pre[t] = *reinterpret_cast<const float4*>(
                    Xg + row * D_IN + (kc + 1) * 64 + q * 4);
            }
        }
        #pragma unroll
        for (int k8 = 0; k8 < 8; ++k8) {
            const int k8g = kc * 8 + k8;
            const int cur = k8g & 1;
            const int nk  = (k8g < 31) ? k8g + 1 : 31;   // prefetch next B frags
            #pragma unroll
            for (int nt = 0; nt < 4; ++nt) {
                float2 w2 = __ldg(&g_wfrag[(nk * 16 + nq * 4 + nt) * 32 + lane]);
                bfr[cur ^ 1][nt][0] = __float_as_uint(w2.x);
                bfr[cur ^ 1][nt][1] = __float_as_uint(w2.y);
            }
            const int kl = k8 * 8;
            uint32_t af[2][4];
            #pragma unroll
            for (int mt = 0; mt < 2; ++mt) {
                const float* p = Xs + (m0 + mt * 16 + lr) * X_ST + kl + lc;
                af[mt][0] = __float_as_uint(p[0]);
                af[mt][1] = __float_as_uint(p[8 * X_ST]);
                af[mt][2] = __float_as_uint(p[4]);
                af[mt][3] = __float_as_uint(p[8 * X_ST + 4]);
            }
            #pragma unroll
            for (int mt = 0; mt < 2; ++mt)
                #pragma unroll
                for (int nt = 0; nt < 4; ++nt)
                    mma8(acc[mt][nt], af[mt], bfr[cur][nt]);
        }
    }

    // epilogue: h (+bias), tf32-rounded -> smem
    #pragma unroll
    for (int mt = 0; mt < 2; ++mt) {
        #pragma unroll
        for (int nt = 0; nt < 4; ++nt) {
            int row = m0 + mt * 16 + lr;
            int col = n0 + nt * 8 + 2 * lc;
            hs[row * H_ST + col]           = tf32r(acc[mt][nt][0] + bs[col]);
            hs[row * H_ST + col + 1]       = tf32r(acc[mt][nt][1] + bs[col + 1]);
            hs[(row + 8) * H_ST + col]     = tf32r(acc[mt][nt][2] + bs[col]);
            hs[(row + 8) * H_ST + col + 1] = tf32r(acc[mt][nt][3] + bs[col + 1]);
        }
    }
    __syncthreads();

    // ================= S = h @ h^T  (64x64, K=128) =================
    float accS[2][2][4];
    #pragma unroll
    for (int mt = 0; mt < 2; ++mt)
        #pragma unroll
        for (int nt = 0; nt < 2; ++nt)
            #pragma unroll
            for (int i = 0; i < 4; ++i) accS[mt][nt][i] = 0.f;

    #pragma unroll
    for (int k8 = 0; k8 < 16; ++k8) {
        const int kl = k8 * 8;
        uint32_t af[2][4];
        #pragma unroll
        for (int mt = 0; mt < 2; ++mt) {
            const float* p = hs + (m0 + mt * 16 + lr) * H_ST + kl + lc;
            af[mt][0] = __float_as_uint(p[0]);
            af[mt][1] = __float_as_uint(p[8 * H_ST]);
            af[mt][2] = __float_as_uint(p[4]);
            af[mt][3] = __float_as_uint(p[8 * H_ST + 4]);
        }
        uint32_t bf[2][2];
        #pragma unroll
        for (int nt = 0; nt < 2; ++nt) {
            const float* p = hs + (n0s + nt * 8 + lr) * H_ST + kl + lc;
            bf[nt][0] = __float_as_uint(p[0]);
            bf[nt][1] = __float_as_uint(p[4]);
        }
        #pragma unroll
        for (int mt = 0; mt < 2; ++mt)
            #pragma unroll
            for (int nt = 0; nt < 2; ++nt)
                mma8(accS[mt][nt], af[mt], bf[nt]);
    }
    // store S raw fp32 (Ss overlays Xs; every warp issued its last Xs read in the
    // GEMM mainloop, which completed before the epilogue __syncthreads())
    #pragma unroll
    for (int mt = 0; mt < 2; ++mt) {
        #pragma unroll
        for (int nt = 0; nt < 2; ++nt) {
            int row = m0 + mt * 16 + lr;
            int col = n0s + nt * 8 + 2 * lc;
            Ss[row * S_ST + col]           = accS[mt][nt][0];
            Ss[row * S_ST + col + 1]       = accS[mt][nt][1];
            Ss[(row + 8) * S_ST + col]     = accS[mt][nt][2];
            Ss[(row + 8) * S_ST + col + 1] = accS[mt][nt][3];
        }
    }
    __syncthreads();

    // ================= softmax (row-wise), in place, P tf32 =================
    {
        const int srow = tid >> 2;      // 64 rows, 4 threads/row
        const int sq   = tid & 3;
        float4* rp = reinterpret_cast<float4*>(Ss + srow * S_ST + sq * 16);
        float v[16];
        #pragma unroll
        for (int j = 0; j < 4; ++j) {
            float4 t = rp[j];
            v[4*j] = t.x; v[4*j+1] = t.y; v[4*j+2] = t.z; v[4*j+3] = t.w;
        }
        float m = v[0];
        #pragma unroll
        for (int i = 1; i < 16; ++i) m = fmaxf(m, v[i]);
        m = fmaxf(m, __shfl_xor_sync(0xffffffffu, m, 1));
        m = fmaxf(m, __shfl_xor_sync(0xffffffffu, m, 2));
        float s = 0.f;
        #pragma unroll
        for (int i = 0; i < 16; ++i) { v[i] = __expf(v[i] - m); s += v[i]; }
        s += __shfl_xor_sync(0xffffffffu, s, 1);
        s += __shfl_xor_sync(0xffffffffu, s, 2);
        const float inv = 1.0f / s;
        #pragma unroll
        for (int j = 0; j < 4; ++j) {
            rp[j] = make_float4(tf32r(v[4*j] * inv),   tf32r(v[4*j+1] * inv),
                                tf32r(v[4*j+2] * inv), tf32r(v[4*j+3] * inv));
        }
    }
    __syncthreads();

    // ================= ctx = P(64x64) @ h(64x128) =================
    #pragma unroll
    for (int mt = 0; mt < 2; ++mt)
        #pragma unroll
        for (int nt = 0; nt < 4; ++nt)
            #pragma unroll
            for (int i = 0; i < 4; ++i) acc[mt][nt][i] = 0.f;

    #pragma unroll
    for (int k8 = 0; k8 < 8; ++k8) {
        const int kl = k8 * 8;
        uint32_t af[2][4];
        #pragma unroll
        for (int mt = 0; mt < 2; ++mt) {
            const float* p = Ss + (m0 + mt * 16 + lr) * S_ST + kl + lc;
            af[mt][0] = __float_as_uint(p[0]);
            af[mt][1] = __float_as_uint(p[8 * S_ST]);
            af[mt][2] = __float_as_uint(p[4]);
            af[mt][3] = __float_as_uint(p[8 * S_ST + 4]);
        }
        uint32_t bf[4][2];
        #pragma unroll
        for (int nt = 0; nt < 4; ++nt) {
            const float* p = hs + (kl + lc) * H_ST + n0 + nt * 8 + lr;
            bf[nt][0] = __float_as_uint(p[0]);
            bf[nt][1] = __float_as_uint(p[4 * H_ST]);
        }
        #pragma unroll
        for (int mt = 0; mt < 2; ++mt)
            #pragma unroll
            for (int nt = 0; nt < 4; ++nt)
                mma8(acc[mt][nt], af[mt], bf[nt]);
    }

    // store ctx to gmem
    #pragma unroll
    for (int mt = 0; mt < 2; ++mt) {
        #pragma unroll
        for (int nt = 0; nt < 4; ++nt) {
            size_t row = (size_t)g * SEGSZ + m0 + mt * 16 + lr;
            int col = n0 + nt * 8 + 2 * lc;
            *reinterpret_cast<float2*>(out + row * D_OUT + col) =
                make_float2(acc[mt][nt][0], acc[mt][nt][1]);
            *reinterpret_cast<float2*>(out + (row + 8) * D_OUT + col) =
                make_float2(acc[mt][nt][2], acc[mt][nt][3]);
        }
    }
}

extern "C" void kernel_launch(void* const* d_in, const int* in_sizes, int n_in,
                              void* d_out, int out_size) {
    (void)in_sizes; (void)n_in; (void)out_size;
    const float* X = (const float*)d_in[0];
    const float* W = (const float*)d_in[1];
    const float* b = (const float*)d_in[2];
    float* out = (float*)d_out;

    prep_w_kernel<<<64, 256>>>(W);   // 16384 fragment float2s

    cudaFuncSetAttribute(attn_hidden_kernel,
                         cudaFuncAttributeMaxDynamicSharedMemorySize, SMEM_BYTES);
    attn_hidden_kernel<<<N_SEQ, 256, SMEM_BYTES>>>(X, b, out);
}

// round 14
// speedup vs baseline: 2.2086x; 1.5727x over previous
#include <cuda_runtime.h>
#include <cuda_fp16.h>
#include <cstdint>

#define D_IN 256
#define D_OUT 128
#define SEGSZ 64
#define N_SEQ 2048

namespace {
// Row strides in BYTES. All satisfy (stride/4) % 32 == 4 so that fragment
// loads across a warp (8 rows x 4 cols) hit banks 4*lr+lc -> conflict-free.
constexpr int X_STB = 528;    // X: 256 halves + pad
constexpr int H_STB = 272;    // h row-major: 128 halves + pad
constexpr int T_STB = 144;    // h transposed: 64 halves + pad
constexpr int P_STB = 144;    // P row-major: 64 halves + pad
constexpr int S_STF = 68;     // S fp32 stride in floats

constexpr int OFF_X  = 0;                   // 64*528  = 33792 B
constexpr int OFF_S  = 0;                   // Ss (64*68*4=17408) overlays Xs (phase-disjoint)
constexpr int OFF_H  = 33792;               // 64*272  = 17408
constexpr int OFF_T  = OFF_H + 17408;       // 51200: 128*144 = 18432
constexpr int OFF_P  = OFF_T + 18432;       // 69632: 64*144  = 9216
constexpr int OFF_BS = OFF_P + 9216;        // 78848: 512
constexpr int SMEM_BYTES = OFF_BS + 512;    // 79360 B -> 2 CTAs/SM
} // namespace

// W in fp16 MMA B-fragment layout:
// g_wfrag16[(kk*16 + ng)*32 + lane] = uint2{
//   half2( W[kk*16+2lc  ][ng*8+lr], W[kk*16+2lc+1][ng*8+lr] ),
//   half2( W[kk*16+2lc+8][ng*8+lr], W[kk*16+2lc+9][ng*8+lr] ) }
__device__ uint2 g_wfrag16[16 * 16 * 32];   // 64 KB

__device__ __forceinline__ uint32_t h2bits(__half2 h) {
    return *reinterpret_cast<uint32_t*>(&h);
}

__device__ __forceinline__ void hmma(float* d, const uint32_t* a, const uint32_t* b) {
    asm volatile(
        "mma.sync.aligned.m16n8k16.row.col.f32.f16.f16.f32 "
        "{%0,%1,%2,%3}, {%4,%5,%6,%7}, {%8,%9}, {%0,%1,%2,%3};\n"
        : "+f"(d[0]), "+f"(d[1]), "+f"(d[2]), "+f"(d[3])
        : "r"(a[0]), "r"(a[1]), "r"(a[2]), "r"(a[3]), "r"(b[0]), "r"(b[1]));
}

__global__ __launch_bounds__(256)
void prep_w_kernel(const float* __restrict__ Wg) {
    int i = blockIdx.x * 256 + threadIdx.x;   // 0..8191
    int kk = i >> 9;          // 0..15
    int ng = (i >> 5) & 15;
    int ln = i & 31;
    int lr = ln >> 2, lc = ln & 3;
    int col = ng * 8 + lr;
    int k = kk * 16;
    __half2 b0 = __floats2half2_rn(Wg[(k + 2*lc    ) * D_OUT + col],
                                   Wg[(k + 2*lc + 1) * D_OUT + col]);
    __half2 b1 = __floats2half2_rn(Wg[(k + 2*lc + 8) * D_OUT + col],
                                   Wg[(k + 2*lc + 9) * D_OUT + col]);
    uint2 v;
    v.x = *reinterpret_cast<uint32_t*>(&b0);
    v.y = *reinterpret_cast<uint32_t*>(&b1);
    g_wfrag16[i] = v;
}

__global__ __launch_bounds__(256, 2)
void attn_hidden_kernel(const float* __restrict__ Xall,
                        const float* __restrict__ bg,
                        float* __restrict__ out)
{
    extern __shared__ char sm[];
    float* Ss = reinterpret_cast<float*>(sm + OFF_S);
    float* bs = reinterpret_cast<float*>(sm + OFF_BS);

    const int tid  = threadIdx.x;
    const int warp = tid >> 5;
    const int lane = tid & 31;
    const int lr   = lane >> 2;
    const int lc   = lane & 3;

    // 2x4 warp grid: GEMM/ctx warp tile = 32 rows x 32 cols; S: 32 x 16
    const int m0  = (warp & 1) * 32;
    const int nq  = warp >> 1;       // 0..3
    const int n0  = nq * 32;
    const int n0s = nq * 16;

    const int g = blockIdx.x;
    const float* Xg = Xall + (size_t)g * SEGSZ * D_IN;

    if (tid < D_OUT) bs[tid] = bg[tid];

    // ---- stage ALL of X (64x256) fp32 -> fp16 smem, once ----
    #pragma unroll 4
    for (int t = 0; t < 16; ++t) {
        int j = tid + t * 256;        // 0..4095 float4s (64 rows x 64 float4)
        int row = j >> 6, q = j & 63;
        float4 x4 = *reinterpret_cast<const float4*>(Xg + row * D_IN + q * 4);
        __half2 h0 = __floats2half2_rn(x4.x, x4.y);
        __half2 h1 = __floats2half2_rn(x4.z, x4.w);
        uint2 v; v.x = h2bits(h0); v.y = h2bits(h1);
        *reinterpret_cast<uint2*>(sm + OFF_X + row * X_STB + q * 8) = v;
    }

    // B-fragment register double buffer (distance 1), W from L1/L2
    uint32_t bfr[2][4][2];
    #pragma unroll
    for (int nt = 0; nt < 4; ++nt) {
        uint2 w = __ldg(&g_wfrag16[(0 * 16 + nq * 4 + nt) * 32 + lane]);
        bfr[0][nt][0] = w.x; bfr[0][nt][1] = w.y;
    }

    __syncthreads();   // Xs + bs ready

    // ================= GEMM: h = X(64x256) @ W(256x128), 16 k16 steps ======
    float acc[2][4][4];
    #pragma unroll
    for (int mt = 0; mt < 2; ++mt)
        #pragma unroll
        for (int nt = 0; nt < 4; ++nt)
            #pragma unroll
            for (int i = 0; i < 4; ++i) acc[mt][nt][i] = 0.f;

    #pragma unroll
    for (int kk = 0; kk < 16; ++kk) {
        const int cur = kk & 1;
        const int nk  = (kk < 15) ? kk + 1 : 15;
        #pragma unroll
        for (int nt = 0; nt < 4; ++nt) {
            uint2 w = __ldg(&g_wfrag16[(nk * 16 + nq * 4 + nt) * 32 + lane]);
            bfr[cur ^ 1][nt][0] = w.x; bfr[cur ^ 1][nt][1] = w.y;
        }
        uint32_t af[2][4];
        #pragma unroll
        for (int mt = 0; mt < 2; ++mt) {
            const char* p = sm + OFF_X + (m0 + mt * 16 + lr) * X_STB + kk * 32 + lc * 4;
            af[mt][0] = *reinterpret_cast<const uint32_t*>(p);
            af[mt][1] = *reinterpret_cast<const uint32_t*>(p + 8 * X_STB);
            af[mt][2] = *reinterpret_cast<const uint32_t*>(p + 16);
            af[mt][3] = *reinterpret_cast<const uint32_t*>(p + 8 * X_STB + 16);
        }
        #pragma unroll
        for (int mt = 0; mt < 2; ++mt)
            #pragma unroll
            for (int nt = 0; nt < 4; ++nt)
                hmma(acc[mt][nt], af[mt], bfr[cur][nt]);
    }

    // epilogue: h (+bias) -> fp16, stored row-major (hs) AND transposed (hT)
    #pragma unroll
    for (int mt = 0; mt < 2; ++mt) {
        #pragma unroll
        for (int nt = 0; nt < 4; ++nt) {
            int row = m0 + mt * 16 + lr;
            int col = n0 + nt * 8 + 2 * lc;
            float d0 = acc[mt][nt][0] + bs[col];
            float d1 = acc[mt][nt][1] + bs[col + 1];
            float d2 = acc[mt][nt][2] + bs[col];
            float d3 = acc[mt][nt][3] + bs[col + 1];
            __half2 p01 = __floats2half2_rn(d0, d1);
            __half2 p23 = __floats2half2_rn(d2, d3);
            *reinterpret_cast<uint32_t*>(sm + OFF_H + row * H_STB + col * 2)       = h2bits(p01);
            *reinterpret_cast<uint32_t*>(sm + OFF_H + (row + 8) * H_STB + col * 2) = h2bits(p23);
            __half* t0 = reinterpret_cast<__half*>(sm + OFF_T + col * T_STB);
            __half* t1 = reinterpret_cast<__half*>(sm + OFF_T + (col + 1) * T_STB);
            t0[row]     = __low2half(p01);  t1[row]     = __high2half(p01);
            t0[row + 8] = __low2half(p23);  t1[row + 8] = __high2half(p23);
        }
    }
    __syncthreads();

    // ================= S = h @ h^T  (64x64, K=128 -> 8 k16 steps) ==========
    float accS[2][2][4];
    #pragma unroll
    for (int mt = 0; mt < 2; ++mt)
        #pragma unroll
        for (int nt = 0; nt < 2; ++nt)
            #pragma unroll
            for (int i = 0; i < 4; ++i) accS[mt][nt][i] = 0.f;

    #pragma unroll
    for (int kk = 0; kk < 8; ++kk) {
        uint32_t af[2][4];
        #pragma unroll
        for (int mt = 0; mt < 2; ++mt) {
            const char* p = sm + OFF_H + (m0 + mt * 16 + lr) * H_STB + kk * 32 + lc * 4;
            af[mt][0] = *reinterpret_cast<const uint32_t*>(p);
            af[mt][1] = *reinterpret_cast<const uint32_t*>(p + 8 * H_STB);
            af[mt][2] = *reinterpret_cast<const uint32_t*>(p + 16);
            af[mt][3] = *reinterpret_cast<const uint32_t*>(p + 8 * H_STB + 16);
        }
        uint32_t bf[2][2];
        #pragma unroll
        for (int nt = 0; nt < 2; ++nt) {
            const char* q = sm + OFF_H + (n0s + nt * 8 + lr) * H_STB + kk * 32 + lc * 4;
            bf[nt][0] = *reinterpret_cast<const uint32_t*>(q);
            bf[nt][1] = *reinterpret_cast<const uint32_t*>(q + 16);
        }
        #pragma unroll
        for (int mt = 0; mt < 2; ++mt)
            #pragma unroll
            for (int nt = 0; nt < 2; ++nt)
                hmma(accS[mt][nt], af[mt], bf[nt]);
    }
    // store S fp32 (Ss overlays Xs; all warps are past their last Xs read)
    #pragma unroll
    for (int mt = 0; mt < 2; ++mt) {
        #pragma unroll
        for (int nt = 0; nt < 2; ++nt) {
            int row = m0 + mt * 16 + lr;
            int col = n0s + nt * 8 + 2 * lc;
            Ss[row * S_STF + col]           = accS[mt][nt][0];
            Ss[row * S_STF + col + 1]       = accS[mt][nt][1];
            Ss[(row + 8) * S_STF + col]     = accS[mt][nt][2];
            Ss[(row + 8) * S_STF + col + 1] = accS[mt][nt][3];
        }
    }
    __syncthreads();

    // ================= softmax (fp32), write P as fp16 =====================
    {
        const int srow = tid >> 2;      // 64 rows, 4 threads/row (16 cols each)
        const int sq   = tid & 3;
        const float4* rp = reinterpret_cast<const float4*>(Ss + srow * S_STF + sq * 16);
        float v[16];
        #pragma unroll
        for (int j = 0; j < 4; ++j) {
            float4 t = rp[j];
            v[4*j] = t.x; v[4*j+1] = t.y; v[4*j+2] = t.z; v[4*j+3] = t.w;
        }
        float m = v[0];
        #pragma unroll
        for (int i = 1; i < 16; ++i) m = fmaxf(m, v[i]);
        m = fmaxf(m, __shfl_xor_sync(0xffffffffu, m, 1));
        m = fmaxf(m, __shfl_xor_sync(0xffffffffu, m, 2));
        float s = 0.f;
        #pragma unroll
        for (int i = 0; i < 16; ++i) { v[i] = __expf(v[i] - m); s += v[i]; }
        s += __shfl_xor_sync(0xffffffffu, s, 1);
        s += __shfl_xor_sync(0xffffffffu, s, 2);
        const float inv = 1.0f / s;
        uint32_t pw[8];
        #pragma unroll
        for (int j = 0; j < 8; ++j) {
            __half2 h = __floats2half2_rn(v[2*j] * inv, v[2*j+1] * inv);
            pw[j] = h2bits(h);
        }
        char* dst = sm + OFF_P + srow * P_STB + sq * 32;
        *reinterpret_cast<uint4*>(dst)      = make_uint4(pw[0], pw[1], pw[2], pw[3]);
        *reinterpret_cast<uint4*>(dst + 16) = make_uint4(pw[4], pw[5], pw[6], pw[7]);
    }
    __syncthreads();

    // ================= ctx = P(64x64) @ h(64x128), 4 k16 steps =============
    #pragma unroll
    for (int mt = 0; mt < 2; ++mt)
        #pragma unroll
        for (int nt = 0; nt < 4; ++nt)
            #pragma unroll
            for (int i = 0; i < 4; ++i) acc[mt][nt][i] = 0.f;

    #pragma unroll
    for (int kk = 0; kk < 4; ++kk) {
        uint32_t af[2][4];
        #pragma unroll
        for (int mt = 0; mt < 2; ++mt) {
            const char* p = sm + OFF_P + (m0 + mt * 16 + lr) * P_STB + kk * 32 + lc * 4;
            af[mt][0] = *reinterpret_cast<const uint32_t*>(p);
            af[mt][1] = *reinterpret_cast<const uint32_t*>(p + 8 * P_STB);
            af[mt][2] = *reinterpret_cast<const uint32_t*>(p + 16);
            af[mt][3] = *reinterpret_cast<const uint32_t*>(p + 8 * P_STB + 16);
        }
        uint32_t bf[4][2];
        #pragma unroll
        for (int nt = 0; nt < 4; ++nt) {
            const char* q = sm + OFF_T + (n0 + nt * 8 + lr) * T_STB + kk * 32 + lc * 4;
            bf[nt][0] = *reinterpret_cast<const uint32_t*>(q);
            bf[nt][1] = *reinterpret_cast<const uint32_t*>(q + 16);
        }
        #pragma unroll
        for (int mt = 0; mt < 2; ++mt)
            #pragma unroll
            for (int nt = 0; nt < 4; ++nt)
                hmma(acc[mt][nt], af[mt], bf[nt]);
    }

    // store ctx (fp32) to gmem
    #pragma unroll
    for (int mt = 0; mt < 2; ++mt) {
        #pragma unroll
        for (int nt = 0; nt < 4; ++nt) {
            size_t row = (size_t)g * SEGSZ + m0 + mt * 16 + lr;
            int col = n0 + nt * 8 + 2 * lc;
            *reinterpret_cast<float2*>(out + row * D_OUT + col) =
                make_float2(acc[mt][nt][0], acc[mt][nt][1]);
            *reinterpret_cast<float2*>(out + (row + 8) * D_OUT + col) =
                make_float2(acc[mt][nt][2], acc[mt][nt][3]);
        }
    }
}

extern "C" void kernel_launch(void* const* d_in, const int* in_sizes, int n_in,
                              void* d_out, int out_size) {
    (void)in_sizes; (void)n_in; (void)out_size;
    const float* X = (const float*)d_in[0];
    const float* W = (const float*)d_in[1];
    const float* b = (const float*)d_in[2];
    float* out = (float*)d_out;

    prep_w_kernel<<<32, 256>>>(W);   // 8192 uint2 fragments (64 KB)

    cudaFuncSetAttribute(attn_hidden_kernel,
                         cudaFuncAttributeMaxDynamicSharedMemorySize, SMEM_BYTES);
    attn_hidden_kernel<<<N_SEQ, 256, SMEM_BYTES>>>(X, b, out);
}